// round 1
// baseline (speedup 1.0000x reference)
#include <cuda_runtime.h>

#define BATCH  32
#define NBOX   8732
#define DDIM   93
#define NCLS   80
#define KC     512
#define NMSMAX 400
#define TOPK   200
#define FLAT   (NCLS*NMSMAX)       // 32000
#define CONF_T 0.01f
#define IOU_T  0.45f

typedef unsigned long long u64;
typedef unsigned int u32;

// ---------------- static scratch (no allocations allowed) ----------------
__device__ float4 g_boxes[BATCH*NBOX];                         // 4.5 MB
__device__ float  g_scoresT[(size_t)BATCH*NCLS*NBOX];          // 89 MB
__device__ u64    g_cands[(size_t)BATCH*NCLS*KC];              // 10.5 MB
__device__ __align__(16) float g_flat[(size_t)BATCH*FLAT*6];   // 24.6 MB
__device__ __align__(16) float g_topscore[(size_t)BATCH*FLAT]; // 4.1 MB
__device__ u64    g_scratch[(size_t)BATCH*FLAT];               // 8.2 MB

// ---------------- kernel 0: zero the padded flat buffers ----------------
__global__ void k_zero() {
    u32 idx = blockIdx.x*blockDim.x + threadIdx.x;
    const u32 NF = (u32)((size_t)BATCH*FLAT*6/4);   // 1,536,000 float4
    float4 z = make_float4(0.f,0.f,0.f,0.f);
    if (idx < NF) {
        ((float4*)g_flat)[idx] = z;
    } else {
        u32 j = idx - NF;
        if (j < (u32)((size_t)BATCH*FLAT/4)) ((float4*)g_topscore)[j] = z;
    }
}

// ---------------- kernel 1: decode boxes + transpose scores ----------------
#define TILE_N 64
__global__ void k_decode(const float* __restrict__ y) {
    __shared__ float t[TILE_N*DDIM];          // 23808 B
    int b  = blockIdx.y;
    int n0 = blockIdx.x * TILE_N;
    int nn = min(TILE_N, NBOX - n0);
    const float* src = y + ((size_t)b*NBOX + n0)*DDIM;
    for (int i = threadIdx.x; i < nn*DDIM; i += blockDim.x) t[i] = src[i];
    __syncthreads();

    if (threadIdx.x < nn) {
        const float* r = t + threadIdx.x*DDIM;
        float aw = r[87], ah = r[88];
        // exact op-order replication of the JAX reference (no FMA contraction)
        float cx = __fadd_rn(__fmul_rn(__fmul_rn(r[81], r[89]), aw), r[85]);
        float cy = __fadd_rn(__fmul_rn(__fmul_rn(r[82], r[90]), ah), r[86]);
        float w  = __fmul_rn(expf(__fmul_rn(r[83], r[91])), aw);
        float h  = __fmul_rn(expf(__fmul_rn(r[84], r[92])), ah);
        float xmin = __fmul_rn(__fsub_rn(cx, __fmul_rn(0.5f, w)), 512.0f);
        float ymin = __fmul_rn(__fsub_rn(cy, __fmul_rn(0.5f, h)), 512.0f);
        float xmax = __fmul_rn(__fadd_rn(cx, __fmul_rn(0.5f, w)), 512.0f);
        float ymax = __fmul_rn(__fadd_rn(cy, __fmul_rn(0.5f, h)), 512.0f);
        g_boxes[(size_t)b*NBOX + n0 + threadIdx.x] = make_float4(xmin, ymin, xmax, ymax);
    }
    // transpose scores: classes 1..80 -> g_scoresT[(b*C+c)*N + n]
    for (int idx = threadIdx.x; idx < NCLS*TILE_N; idx += blockDim.x) {
        int c = idx / TILE_N, i = idx % TILE_N;
        if (i < nn)
            g_scoresT[((size_t)(b*NCLS + c))*NBOX + n0 + i] = t[i*DDIM + 1 + c];
    }
}

// ---------------- kernel 2: per-(b,c) top-512 sorted selection ----------------
// composite key: hi32 = score bits (0 if invalid), lo32 = ~n  -> desc sort gives
// score desc, index asc on ties; invalid (hi=0) after valid, in index order.
__global__ void k_select() {
    __shared__ u64 cur[KC];
    __shared__ u64 chk[KC];
    int task = blockIdx.x;              // b*NCLS + c
    int t = threadIdx.x;                // 0..255
    const float* sc = g_scoresT + (size_t)task*NBOX;

    cur[t] = 0ULL; cur[t+256] = 0ULL;
    __syncthreads();

    const int nch = (NBOX + KC - 1)/KC;     // 18
    for (int cidx = 0; cidx < nch; ++cidx) {
        int base = cidx*KC;
        #pragma unroll
        for (int r = 0; r < 2; ++r) {
            int i = t + r*256;
            int n = base + i;
            u64 key = 0ULL;
            if (n < NBOX) {
                float s = sc[n];
                u32 lo = 0xFFFFFFFFu - (u32)n;
                if (s > CONF_T) key = ((u64)__float_as_uint(s) << 32) | (u64)lo;
                else            key = (u64)lo;      // hi = 0
            }
            chk[i] = key;
        }
        __syncthreads();
        // bitonic sort chunk ascending
        for (int kk = 2; kk <= KC; kk <<= 1) {
            for (int j = kk >> 1; j > 0; j >>= 1) {
                int i = ((t & ~(j-1)) << 1) | (t & (j-1));
                int p = i | j;
                bool up = ((i & kk) == 0);
                u64 a = chk[i], bb = chk[p];
                bool sw = up ? (a > bb) : (a < bb);
                if (sw) { chk[i] = bb; chk[p] = a; }
                __syncthreads();
            }
        }
        // max(desc cur, asc chunk) = bitonic top-512 of the union
        #pragma unroll
        for (int r = 0; r < 2; ++r) {
            int i = t + r*256;
            u64 a = cur[i], bb = chk[i];
            cur[i] = (a > bb) ? a : bb;
        }
        __syncthreads();
        // bitonic merge descending
        for (int j = KC >> 1; j > 0; j >>= 1) {
            int i = ((t & ~(j-1)) << 1) | (t & (j-1));
            int p = i | j;
            u64 a = cur[i], bb = cur[p];
            if (a < bb) { cur[i] = bb; cur[p] = a; }
            __syncthreads();
        }
    }
    g_cands[(size_t)task*KC + t]       = cur[t];
    g_cands[(size_t)task*KC + t + 256] = cur[t + 256];
}

// ---------------- kernel 3: greedy NMS, one warp per (b,c) ----------------
#define NMS_WARPS 3
__global__ void k_nms() {
    __shared__ float s_f[NMS_WARPS*6*KC];     // 36864 B
    __shared__ short s_kept[NMS_WARPS*KC];    //  3072 B
    int warp = threadIdx.y, lane = threadIdx.x;
    int task = blockIdx.x*NMS_WARPS + warp;
    if (task >= BATCH*NCLS) return;
    int b = task / NCLS, c = task % NCLS;

    float* X1 = s_f + warp*6*KC;
    float* Y1 = X1 + KC; float* X2 = Y1 + KC; float* Y2 = X2 + KC;
    float* AR = Y2 + KC; float* SC = AR + KC;
    short* KP = s_kept + warp*KC;

    const u64* cand = g_cands + (size_t)task*KC;
    int nv = 0;
    for (int r = 0; r < KC/32; ++r) {
        int i = r*32 + lane;
        u64 key = cand[i];
        u32 hi = (u32)(key >> 32);
        bool v = (hi != 0u);
        nv += __popc(__ballot_sync(0xFFFFFFFFu, v));
        float4 bx = make_float4(0.f,0.f,0.f,0.f);
        if (v) {
            u32 n = 0xFFFFFFFFu - (u32)key;
            bx = g_boxes[(size_t)b*NBOX + n];
        }
        X1[i]=bx.x; Y1[i]=bx.y; X2[i]=bx.z; Y2[i]=bx.w;
        AR[i] = __fmul_rn(__fsub_rn(bx.z,bx.x), __fsub_rn(bx.w,bx.y));
        SC[i] = __uint_as_float(hi);
    }
    __syncwarp();

    int m = 0;
    for (int j = 0; j < nv; ++j) {
        if (m >= NMSMAX) break;
        float jx1=X1[j], jy1=Y1[j], jx2=X2[j], jy2=Y2[j], ja=AR[j];
        bool sup = false;
        for (int base = 0; base < m && !sup; base += 32) {
            int p = base + lane;
            bool hit = false;
            if (p < m) {
                int ki = KP[p];
                float ix1 = fmaxf(jx1, X1[ki]);
                float iy1 = fmaxf(jy1, Y1[ki]);
                float ix2 = fminf(jx2, X2[ki]);
                float iy2 = fminf(jy2, Y2[ki]);
                float dw = fmaxf(__fsub_rn(ix2, ix1), 0.0f);
                float dh = fmaxf(__fsub_rn(iy2, iy1), 0.0f);
                float inter = __fmul_rn(dw, dh);
                float uni = __fsub_rn(__fadd_rn(ja, AR[ki]), inter);
                if (uni > 0.0f) hit = (__fdiv_rn(inter, uni) > IOU_T);
            }
            sup = (__ballot_sync(0xFFFFFFFFu, hit) != 0u);
        }
        if (!sup) {
            if (lane == 0) KP[m] = (short)j;
            m++;
            __syncwarp();
        }
    }
    // compact kept entries to front of this class block
    for (int p = lane; p < m; p += 32) {
        int j = KP[p];
        size_t o = (size_t)b*FLAT + c*NMSMAX + p;
        g_topscore[o] = SC[j];
        float* e = g_flat + o*6;
        e[0] = (float)(c+1);
        e[1] = SC[j];
        e[2] = X1[j]; e[3] = Y1[j]; e[4] = X2[j]; e[5] = Y2[j];
    }
}

// ---------------- kernel 4: per-batch top-200 ----------------
__global__ void k_topk(float* __restrict__ out) {
    __shared__ u64 cur[256];
    __shared__ u64 chk[KC];
    __shared__ int s_cnt;
    int b = blockIdx.x, t = threadIdx.x;    // 256 threads
    if (t == 0) s_cnt = 0;
    __syncthreads();

    const float* sc = g_topscore + (size_t)b*FLAT;
    u64* scratch = g_scratch + (size_t)b*FLAT;
    for (int i = t; i < FLAT; i += 256) {
        float s = sc[i];
        if (s > 0.0f) {
            int p = atomicAdd(&s_cnt, 1);
            scratch[p] = ((u64)__float_as_uint(s) << 32) | (u64)(0xFFFFFFFFu - (u32)i);
        }
    }
    __syncthreads();
    int n = s_cnt;
    bool full = (n < TOPK);                 // rare fallback: scan all slots (incl. zeros)
    int total = full ? FLAT : n;

    cur[t] = 0ULL;
    __syncthreads();

    int nch = (total + KC - 1)/KC;
    for (int cidx = 0; cidx < nch; ++cidx) {
        int base = cidx*KC;
        #pragma unroll
        for (int r = 0; r < 2; ++r) {
            int i = t + r*256;
            int g = base + i;
            u64 key = 0ULL;
            if (g < total) {
                if (full) {
                    float s = sc[g];
                    key = ((u64)__float_as_uint(s) << 32) | (u64)(0xFFFFFFFFu - (u32)g);
                } else {
                    key = scratch[g];
                }
            }
            chk[i] = key;
        }
        __syncthreads();
        // sort 512-chunk ascending
        for (int kk = 2; kk <= KC; kk <<= 1) {
            for (int j = kk >> 1; j > 0; j >>= 1) {
                int i = ((t & ~(j-1)) << 1) | (t & (j-1));
                int p = i | j;
                bool up = ((i & kk) == 0);
                u64 a = chk[i], bb = chk[p];
                bool sw = up ? (a > bb) : (a < bb);
                if (sw) { chk[i] = bb; chk[p] = a; }
                __syncthreads();
            }
        }
        // combine cur(256 desc) with chunk's top-256 = chk[256..511] (asc)
        {
            u64 a = cur[t], bb = chk[256 + t];
            cur[t] = (a > bb) ? a : bb;
            __syncthreads();
        }
        // bitonic merge descending on 256
        for (int j = 128; j > 0; j >>= 1) {
            if (t < 128) {
                int i = ((t & ~(j-1)) << 1) | (t & (j-1));
                int p = i | j;
                u64 a = cur[i], bb = cur[p];
                if (a < bb) { cur[i] = bb; cur[p] = a; }
            }
            __syncthreads();
        }
    }
    // gather top-200 rows
    for (int idx = t; idx < TOPK*6; idx += 256) {
        int k = idx / 6, r = idx % 6;
        u64 key = cur[k];
        u32 flat = 0xFFFFFFFFu - (u32)key;
        out[((size_t)b*TOPK + k)*6 + r] = g_flat[((size_t)b*FLAT + flat)*6 + r];
    }
}

// ---------------- launcher ----------------
extern "C" void kernel_launch(void* const* d_in, const int* in_sizes, int n_in,
                              void* d_out, int out_size) {
    const float* y = (const float*)d_in[0];
    float* out = (float*)d_out;

    k_zero<<<7000, 256>>>();                                  // 7000*256 = 1,792,000 float4 exactly
    k_decode<<<dim3((NBOX + TILE_N - 1)/TILE_N, BATCH), 256>>>(y);
    k_select<<<BATCH*NCLS, 256>>>();
    k_nms<<<(BATCH*NCLS + NMS_WARPS - 1)/NMS_WARPS, dim3(32, NMS_WARPS)>>>();
    k_topk<<<BATCH, 256>>>(out);
}

// round 2
// speedup vs baseline: 1.1456x; 1.1456x over previous
#include <cuda_runtime.h>

#define BATCH  32
#define NBOX   8732
#define DDIM   93
#define NCLS   80
#define KC     512
#define NMSMAX 400
#define TOPK   200
#define FLAT   (NCLS*NMSMAX)       // 32000
#define CONF_T 0.01f
#define IOU_T  0.45f

typedef unsigned long long u64;
typedef unsigned int u32;

#define SK(i) ((i) + ((i) >> 5))   // skewed smem index (bank-conflict relief)
#define KSK   (KC + KC/32)         // 528

// ---------------- static scratch (no allocations allowed) ----------------
__device__ float4 g_boxes[BATCH*NBOX];                         // 4.5 MB
__device__ float  g_scoresT[(size_t)BATCH*NCLS*NBOX];          // 89 MB
__device__ u64    g_cands[(size_t)BATCH*NCLS*KC];              // 10.5 MB
__device__ __align__(16) float g_flat[(size_t)BATCH*FLAT*6];   // 24.6 MB
__device__ __align__(16) float g_topscore[(size_t)BATCH*FLAT]; // 4.1 MB
__device__ u64    g_scratch[(size_t)BATCH*FLAT];               // 8.2 MB

// ---------------- kernel 0: zero the padded flat buffers ----------------
__global__ void k_zero() {
    u32 idx = blockIdx.x*blockDim.x + threadIdx.x;
    const u32 NF = (u32)((size_t)BATCH*FLAT*6/4);   // 1,536,000 float4
    float4 z = make_float4(0.f,0.f,0.f,0.f);
    if (idx < NF) {
        ((float4*)g_flat)[idx] = z;
    } else {
        u32 j = idx - NF;
        if (j < (u32)((size_t)BATCH*FLAT/4)) ((float4*)g_topscore)[j] = z;
    }
}

// ---------------- kernel 1: decode boxes + transpose scores ----------------
#define TILE_N 64
__global__ void k_decode(const float* __restrict__ y) {
    __shared__ float t[TILE_N*DDIM];          // 23808 B
    int b  = blockIdx.y;
    int n0 = blockIdx.x * TILE_N;
    int nn = min(TILE_N, NBOX - n0);
    const float* src = y + ((size_t)b*NBOX + n0)*DDIM;
    for (int i = threadIdx.x; i < nn*DDIM; i += blockDim.x) t[i] = src[i];
    __syncthreads();

    if (threadIdx.x < nn) {
        const float* r = t + threadIdx.x*DDIM;
        float aw = r[87], ah = r[88];
        // exact op-order replication of the JAX reference (no FMA contraction)
        float cx = __fadd_rn(__fmul_rn(__fmul_rn(r[81], r[89]), aw), r[85]);
        float cy = __fadd_rn(__fmul_rn(__fmul_rn(r[82], r[90]), ah), r[86]);
        float w  = __fmul_rn(expf(__fmul_rn(r[83], r[91])), aw);
        float h  = __fmul_rn(expf(__fmul_rn(r[84], r[92])), ah);
        float xmin = __fmul_rn(__fsub_rn(cx, __fmul_rn(0.5f, w)), 512.0f);
        float ymin = __fmul_rn(__fsub_rn(cy, __fmul_rn(0.5f, h)), 512.0f);
        float xmax = __fmul_rn(__fadd_rn(cx, __fmul_rn(0.5f, w)), 512.0f);
        float ymax = __fmul_rn(__fadd_rn(cy, __fmul_rn(0.5f, h)), 512.0f);
        g_boxes[(size_t)b*NBOX + n0 + threadIdx.x] = make_float4(xmin, ymin, xmax, ymax);
    }
    // transpose scores: classes 1..80 -> g_scoresT[(b*C+c)*N + n]
    for (int idx = threadIdx.x; idx < NCLS*TILE_N; idx += blockDim.x) {
        int c = idx / TILE_N, i = idx % TILE_N;
        if (i < nn)
            g_scoresT[((size_t)(b*NCLS + c))*NBOX + n0 + i] = t[i*DDIM + 1 + c];
    }
}

// ---------------- kernel 2: per-(b,c) top-512 sorted selection ----------------
// composite key: hi32 = score bits (0 if invalid), lo32 = ~n  -> desc sort gives
// score desc, index asc on ties; invalid (hi=0) after valid, in index order.
// Bitonic layers with stride j<=16 are warp-local (warp w owns elements
// [64w,64w+64)), so only j>=32 layers need a full block barrier.
__global__ void k_select() {
    __shared__ u64 cur[KSK];
    __shared__ u64 chk[KSK];
    int task = blockIdx.x;              // b*NCLS + c
    int t = threadIdx.x;                // 0..255
    const float* sc = g_scoresT + (size_t)task*NBOX;

    cur[SK(t)] = 0ULL; cur[SK(t+256)] = 0ULL;
    __syncthreads();

    const int nch = (NBOX + KC - 1)/KC;     // 18
    for (int cidx = 0; cidx < nch; ++cidx) {
        int base = cidx*KC;
        #pragma unroll
        for (int r = 0; r < 2; ++r) {
            int i = t + r*256;
            int n = base + i;
            u64 key = 0ULL;
            if (n < NBOX) {
                float s = sc[n];
                u32 lo = 0xFFFFFFFFu - (u32)n;
                if (s > CONF_T) key = ((u64)__float_as_uint(s) << 32) | (u64)lo;
                else            key = (u64)lo;      // hi = 0
            }
            chk[SK(i)] = key;
        }
        __syncthreads();
        // bitonic sort chunk ascending
        for (int kk = 2; kk <= KC; kk <<= 1) {
            for (int j = kk >> 1; j > 0; j >>= 1) {
                if (j >= 32) __syncthreads(); else __syncwarp();
                int i = ((t & ~(j-1)) << 1) | (t & (j-1));
                int p = i | j;
                bool up = ((i & kk) == 0);
                u64 a = chk[SK(i)], bb = chk[SK(p)];
                if (up ? (a > bb) : (a < bb)) { chk[SK(i)] = bb; chk[SK(p)] = a; }
            }
        }
        __syncthreads();
        // max(desc cur, asc chunk) = bitonic top-512 of the union
        #pragma unroll
        for (int r = 0; r < 2; ++r) {
            int i = t + r*256;
            u64 a = cur[SK(i)], bb = chk[SK(i)];
            cur[SK(i)] = (a > bb) ? a : bb;
        }
        // bitonic merge descending
        for (int j = KC >> 1; j > 0; j >>= 1) {
            if (j >= 32) __syncthreads(); else __syncwarp();
            int i = ((t & ~(j-1)) << 1) | (t & (j-1));
            int p = i | j;
            u64 a = cur[SK(i)], bb = cur[SK(p)];
            if (a < bb) { cur[SK(i)] = bb; cur[SK(p)] = a; }
        }
        __syncthreads();
    }
    g_cands[(size_t)task*KC + t]       = cur[SK(t)];
    g_cands[(size_t)task*KC + t + 256] = cur[SK(t + 256)];
}

// ---------------- kernel 3: frontier greedy NMS, one block per (b,c) ----------------
// Work is proportional to KEPT boxes, not candidates: warp 0 scans a 512-bit
// suppressed mask for the next survivor; all 256 threads then suppress its
// overlaps in parallel (2 block barriers per kept box).
__global__ void k_nms() {
    __shared__ float X1[KC], Y1[KC], X2[KC], Y2[KC], AR[KC], SC[KC];
    __shared__ u32 sup[16];
    __shared__ short KP[NMSMAX];
    __shared__ int s_next, s_nv;
    int task = blockIdx.x;
    int b = task / NCLS, c = task % NCLS;
    int t = threadIdx.x;                 // 0..255
    int lane = t & 31, warp = t >> 5;

    if (t == 0) s_nv = KC;
    __syncthreads();

    const u64* cand = g_cands + (size_t)task*KC;
    #pragma unroll
    for (int r = 0; r < 2; ++r) {
        int i = t + r*256;
        u64 key = cand[i];
        u32 hi = (u32)(key >> 32);
        float4 bx = make_float4(0.f,0.f,0.f,0.f);
        if (hi != 0u) {
            u32 n = 0xFFFFFFFFu - (u32)key;
            bx = g_boxes[(size_t)b*NBOX + n];
        } else {
            atomicMin(&s_nv, i);
        }
        X1[i]=bx.x; Y1[i]=bx.y; X2[i]=bx.z; Y2[i]=bx.w;
        AR[i] = __fmul_rn(__fsub_rn(bx.z,bx.x), __fsub_rn(bx.w,bx.y));
        SC[i] = __uint_as_float(hi);
    }
    __syncthreads();
    int nv = s_nv;
    if (t < 16) {                        // mark invalid tail as suppressed
        int lo = t*32, hi2 = lo + 32;
        u32 m;
        if      (nv >= hi2) m = 0u;
        else if (nv <= lo)  m = 0xFFFFFFFFu;
        else                m = ~((1u << (nv - lo)) - 1u);
        sup[t] = m;
    }
    __syncthreads();

    int kept = 0;
    int cur = 0;
    while (kept < NMSMAX) {
        if (warp == 0) {                 // find next unsuppressed index >= cur
            u32 w = (lane < 16) ? sup[lane] : 0xFFFFFFFFu;
            int cw = cur >> 5;
            if (lane < cw) w = 0xFFFFFFFFu;
            else if (lane == cw) {
                int cb = cur & 31;
                if (cb) w |= (1u << cb) - 1u;
            }
            u32 avail = ~w;
            u32 has = __ballot_sync(0xFFFFFFFFu, avail != 0u);
            int nxt = KC;
            if (has) {
                int l = __ffs(has) - 1;
                u32 ww = __shfl_sync(0xFFFFFFFFu, avail, l);
                nxt = l*32 + __ffs(ww) - 1;
            }
            if (lane == 0) s_next = nxt;
        }
        __syncthreads();
        int i = s_next;
        if (i >= KC) break;
        if (t == 0) KP[kept] = (short)i;
        kept++;
        cur = i + 1;

        float ix1 = X1[i], iy1 = Y1[i], ix2 = X2[i], iy2 = Y2[i], ia = AR[i];
        u32 hits[2];
        #pragma unroll
        for (int r = 0; r < 2; ++r) {
            int j = t + r*256;
            bool hit = false;
            if (j > i) {
                float xx1 = fmaxf(ix1, X1[j]);
                float yy1 = fmaxf(iy1, Y1[j]);
                float xx2 = fminf(ix2, X2[j]);
                float yy2 = fminf(iy2, Y2[j]);
                float dw = fmaxf(__fsub_rn(xx2, xx1), 0.0f);
                float dh = fmaxf(__fsub_rn(yy2, yy1), 0.0f);
                float inter = __fmul_rn(dw, dh);
                float uni = __fsub_rn(__fadd_rn(ia, AR[j]), inter);
                if (uni > 0.0f) hit = (__fdiv_rn(inter, uni) > IOU_T);
            }
            hits[r] = __ballot_sync(0xFFFFFFFFu, hit);
        }
        if (lane == 0) {                 // warp w owns words w and w+8: no races
            sup[warp]     |= hits[0];
            sup[warp + 8] |= hits[1];
        }
        __syncthreads();
    }

    // compact kept entries to front of this class block
    for (int p = t; p < kept; p += 256) {
        int j = KP[p];
        size_t o = (size_t)b*FLAT + c*NMSMAX + p;
        g_topscore[o] = SC[j];
        float* e = g_flat + o*6;
        e[0] = (float)(c+1);
        e[1] = SC[j];
        e[2] = X1[j]; e[3] = Y1[j]; e[4] = X2[j]; e[5] = Y2[j];
    }
}

// ---------------- kernel 4: per-batch top-200 ----------------
__global__ void k_topk(float* __restrict__ out) {
    __shared__ u64 cur[256];
    __shared__ u64 chk[KC];
    __shared__ int s_cnt;
    int b = blockIdx.x, t = threadIdx.x;    // 256 threads
    if (t == 0) s_cnt = 0;
    __syncthreads();

    const float* sc = g_topscore + (size_t)b*FLAT;
    u64* scratch = g_scratch + (size_t)b*FLAT;
    for (int i = t; i < FLAT; i += 256) {
        float s = sc[i];
        if (s > 0.0f) {
            int p = atomicAdd(&s_cnt, 1);
            scratch[p] = ((u64)__float_as_uint(s) << 32) | (u64)(0xFFFFFFFFu - (u32)i);
        }
    }
    __syncthreads();
    int n = s_cnt;
    bool full = (n < TOPK);                 // rare fallback: scan all slots (incl. zeros)
    int total = full ? FLAT : n;

    cur[t] = 0ULL;
    __syncthreads();

    int nch = (total + KC - 1)/KC;
    for (int cidx = 0; cidx < nch; ++cidx) {
        int base = cidx*KC;
        #pragma unroll
        for (int r = 0; r < 2; ++r) {
            int i = t + r*256;
            int g = base + i;
            u64 key = 0ULL;
            if (g < total) {
                if (full) {
                    float s = sc[g];
                    key = ((u64)__float_as_uint(s) << 32) | (u64)(0xFFFFFFFFu - (u32)g);
                } else {
                    key = scratch[g];
                }
            }
            chk[i] = key;
        }
        __syncthreads();
        // sort 512-chunk ascending
        for (int kk = 2; kk <= KC; kk <<= 1) {
            for (int j = kk >> 1; j > 0; j >>= 1) {
                int i = ((t & ~(j-1)) << 1) | (t & (j-1));
                int p = i | j;
                bool up = ((i & kk) == 0);
                u64 a = chk[i], bb = chk[p];
                bool sw = up ? (a > bb) : (a < bb);
                if (sw) { chk[i] = bb; chk[p] = a; }
                __syncthreads();
            }
        }
        // combine cur(256 desc) with chunk's top-256 = chk[256..511] (asc)
        {
            u64 a = cur[t], bb = chk[256 + t];
            cur[t] = (a > bb) ? a : bb;
            __syncthreads();
        }
        // bitonic merge descending on 256
        for (int j = 128; j > 0; j >>= 1) {
            if (t < 128) {
                int i = ((t & ~(j-1)) << 1) | (t & (j-1));
                int p = i | j;
                u64 a = cur[i], bb = cur[p];
                if (a < bb) { cur[i] = bb; cur[p] = a; }
            }
            __syncthreads();
        }
    }
    // gather top-200 rows
    for (int idx = t; idx < TOPK*6; idx += 256) {
        int k = idx / 6, r = idx % 6;
        u64 key = cur[k];
        u32 flat = 0xFFFFFFFFu - (u32)key;
        out[((size_t)b*TOPK + k)*6 + r] = g_flat[((size_t)b*FLAT + flat)*6 + r];
    }
}

// ---------------- launcher ----------------
extern "C" void kernel_launch(void* const* d_in, const int* in_sizes, int n_in,
                              void* d_out, int out_size) {
    const float* y = (const float*)d_in[0];
    float* out = (float*)d_out;

    k_zero<<<7000, 256>>>();                                  // 7000*256 = 1,792,000 float4 exactly
    k_decode<<<dim3((NBOX + TILE_N - 1)/TILE_N, BATCH), 256>>>(y);
    k_select<<<BATCH*NCLS, 256>>>();
    k_nms<<<BATCH*NCLS, 256>>>();
    k_topk<<<BATCH, 256>>>(out);
}

// round 5
// speedup vs baseline: 1.1764x; 1.0269x over previous
#include <cuda_runtime.h>

#define BATCH  32
#define NBOX   8732
#define DDIM   93
#define NCLS   80
#define KC     512
#define PC     1024            // pending buffer capacity
#define NMSMAX 400
#define TOPK   200
#define FLAT   (NCLS*NMSMAX)   // 32000
#define CONF_T 0.01f
#define IOU_T  0.45f

typedef unsigned long long u64;
typedef unsigned int u32;

#define SK(i) ((i) + ((i) >> 5))   // skewed smem index (bank-conflict relief)

// Barrier before a bitonic layer of stride j: the previous layer's stride was 2j.
// Warp w owns elements [64w,64w+64) for strides <=32; strides >=64 write cross-warp.
// => need __syncthreads iff j >= 32 (guards prev stride-2j>=64 writes AND makes
// warp-local writes visible before a cross-block read at j>=64).
#define LAYER_BAR(j) do { if ((j) >= 32) __syncthreads(); else __syncwarp(); } while (0)

// ---------------- static scratch (no allocations allowed) ----------------
__device__ float4 g_boxes[BATCH*NBOX];
__device__ float  g_scoresT[(size_t)BATCH*NCLS*NBOX];
__device__ u64    g_cands[(size_t)BATCH*NCLS*KC];
__device__ __align__(16) float g_flat[(size_t)BATCH*FLAT*6];
__device__ __align__(16) float g_topscore[(size_t)BATCH*FLAT];
__device__ u64    g_scratch[(size_t)BATCH*FLAT];

// ---------------- kernel 0: zero the padded flat buffers ----------------
__global__ void k_zero() {
    u32 idx = blockIdx.x*blockDim.x + threadIdx.x;
    const u32 NF = (u32)((size_t)BATCH*FLAT*6/4);
    float4 z = make_float4(0.f,0.f,0.f,0.f);
    if (idx < NF) {
        ((float4*)g_flat)[idx] = z;
    } else {
        u32 j = idx - NF;
        if (j < (u32)((size_t)BATCH*FLAT/4)) ((float4*)g_topscore)[j] = z;
    }
}

// ---------------- kernel 1: decode boxes + transpose scores ----------------
#define TILE_N 64
__global__ void k_decode(const float* __restrict__ y) {
    __shared__ float t[TILE_N*DDIM];
    int b  = blockIdx.y;
    int n0 = blockIdx.x * TILE_N;
    int nn = min(TILE_N, NBOX - n0);
    const float* src = y + ((size_t)b*NBOX + n0)*DDIM;
    for (int i = threadIdx.x; i < nn*DDIM; i += blockDim.x) t[i] = src[i];
    __syncthreads();

    if (threadIdx.x < nn) {
        const float* r = t + threadIdx.x*DDIM;
        float aw = r[87], ah = r[88];
        float cx = __fadd_rn(__fmul_rn(__fmul_rn(r[81], r[89]), aw), r[85]);
        float cy = __fadd_rn(__fmul_rn(__fmul_rn(r[82], r[90]), ah), r[86]);
        float w  = __fmul_rn(expf(__fmul_rn(r[83], r[91])), aw);
        float h  = __fmul_rn(expf(__fmul_rn(r[84], r[92])), ah);
        float xmin = __fmul_rn(__fsub_rn(cx, __fmul_rn(0.5f, w)), 512.0f);
        float ymin = __fmul_rn(__fsub_rn(cy, __fmul_rn(0.5f, h)), 512.0f);
        float xmax = __fmul_rn(__fadd_rn(cx, __fmul_rn(0.5f, w)), 512.0f);
        float ymax = __fmul_rn(__fadd_rn(cy, __fmul_rn(0.5f, h)), 512.0f);
        g_boxes[(size_t)b*NBOX + n0 + threadIdx.x] = make_float4(xmin, ymin, xmax, ymax);
    }
    for (int idx = threadIdx.x; idx < NCLS*TILE_N; idx += blockDim.x) {
        int c = idx / TILE_N, i = idx % TILE_N;
        if (i < nn)
            g_scoresT[((size_t)(b*NCLS + c))*NBOX + n0 + i] = t[i*DDIM + 1 + c];
    }
}

// ---------------- kernel 2: per-(b,c) top-512 via threshold-filtered pending ----------------
__global__ void k_select() {
    __shared__ u64 cur[KC + KC/32];     // 528
    __shared__ u64 pend[PC + PC/32];    // 1056
    __shared__ int s_pcnt;
    int task = blockIdx.x;
    int t = threadIdx.x;                // 0..255
    int lane = t & 31;
    const float* sc = g_scoresT + (size_t)task*NBOX;

    cur[SK(t)] = 0ULL; cur[SK(t+256)] = 0ULL;
    #pragma unroll
    for (int r = 0; r < 4; ++r) pend[SK(t + r*256)] = 0ULL;
    if (t == 0) s_pcnt = 0;
    __syncthreads();

    const int nch = (NBOX + KC - 1)/KC;     // 18
    for (int cidx = 0; cidx < nch; ++cidx) {
        u64 thr = cur[SK(KC-1)];
        int base = cidx*KC;
        #pragma unroll
        for (int r = 0; r < 2; ++r) {
            int n = base + t + r*256;
            u64 key = 0ULL;
            if (n < NBOX) {
                float s = sc[n];
                if (s > CONF_T)
                    key = ((u64)__float_as_uint(s) << 32) | (u64)(0xFFFFFFFFu - (u32)n);
            }
            bool pass = key > thr;
            u32 mask = __ballot_sync(0xFFFFFFFFu, pass);
            int rank = __popc(mask & ((1u << lane) - 1u));
            u32 posb = 0;
            if (lane == 0 && mask) posb = atomicAdd(&s_pcnt, __popc(mask));
            posb = __shfl_sync(0xFFFFFFFFu, posb, 0);
            if (pass) {
                u32 pos = posb + rank;
                if (pos < PC) pend[SK(pos)] = key;   // <=1024 by invariant
            }
        }
        __syncthreads();
        int p = s_pcnt;
        __syncthreads();   // all threads latch p before next chunk's atomicAdd
        bool last = (cidx == nch - 1);
        if (p > KC || (last && p > 0)) {
            // bitonic sort pend[0..1024) ascending (zeros pad the front)
            for (int kk = 2; kk <= PC; kk <<= 1) {
                for (int j = kk >> 1; j > 0; j >>= 1) {
                    LAYER_BAR(j);
                    #pragma unroll
                    for (int r = 0; r < 2; ++r) {
                        int pi = t + r*256;
                        int i = ((pi & ~(j-1)) << 1) | (pi & (j-1));
                        int q = i | j;
                        bool up = ((i & kk) == 0);
                        u64 a = pend[SK(i)], bb = pend[SK(q)];
                        if (up ? (a > bb) : (a < bb)) { pend[SK(i)] = bb; pend[SK(q)] = a; }
                    }
                }
            }
            __syncthreads();
            // cur desc (512) + pending top-512 asc (pend[512..1024)) -> max is bitonic
            {
                u64 a = cur[SK(t)],      bb = pend[SK(KC + t)];
                cur[SK(t)] = (a > bb) ? a : bb;
                u64 a2 = cur[SK(t+256)], b2 = pend[SK(KC + t + 256)];
                cur[SK(t+256)] = (a2 > b2) ? a2 : b2;
            }
            // bitonic merge descending on 512 (1 pair/thread)
            for (int j = KC >> 1; j > 0; j >>= 1) {
                LAYER_BAR(j);
                int i = ((t & ~(j-1)) << 1) | (t & (j-1));
                int q = i | j;
                u64 a = cur[SK(i)], bb = cur[SK(q)];
                if (a < bb) { cur[SK(i)] = bb; cur[SK(q)] = a; }
            }
            __syncthreads();
            // reset pending
            #pragma unroll
            for (int r = 0; r < 4; ++r) pend[SK(t + r*256)] = 0ULL;
            if (t == 0) s_pcnt = 0;
            __syncthreads();
        }
    }
    g_cands[(size_t)task*KC + t]       = cur[SK(t)];
    g_cands[(size_t)task*KC + t + 256] = cur[SK(t + 256)];
}

// ---------------- kernel 3: bit-matrix greedy NMS, one block per (b,c) ----------------
__global__ void k_nms() {
    __shared__ float X1[KC], Y1[KC], X2[KC], Y2[KC], AR[KC], SC[KC]; // 12 KB
    __shared__ u32 M[KC*16];                                        // 32 KB
    __shared__ u32 rem[16];
    __shared__ short KP[NMSMAX];
    __shared__ int s_nv, s_kept;
    int task = blockIdx.x;
    int b = task / NCLS, c = task % NCLS;
    int t = threadIdx.x, lane = t & 31;

    if (t == 0) s_nv = KC;
    #pragma unroll
    for (int r = 0; r < 32; ++r) M[t + r*256] = 0u;
    __syncthreads();

    const u64* cand = g_cands + (size_t)task*KC;
    #pragma unroll
    for (int r = 0; r < 2; ++r) {
        int i = t + r*256;
        u64 key = cand[i];
        u32 hi = (u32)(key >> 32);
        float4 bx = make_float4(0.f,0.f,0.f,0.f);
        if (hi != 0u) {
            bx = g_boxes[(size_t)b*NBOX + (0xFFFFFFFFu - (u32)key)];
        } else {
            atomicMin(&s_nv, i);    // keys desc: valid prefix, zero padding after
        }
        X1[i]=bx.x; Y1[i]=bx.y; X2[i]=bx.z; Y2[i]=bx.w;
        AR[i] = __fmul_rn(__fsub_rn(bx.z,bx.x), __fsub_rn(bx.w,bx.y));
        SC[i] = __uint_as_float(hi);
    }
    __syncthreads();
    int nv = s_nv;

    #pragma unroll
    for (int rr = 0; rr < 2; ++rr) {
        int i = rr ? (KC-1-t) : t;
        if (i < nv - 1) {
            float ix1=X1[i], iy1=Y1[i], ix2=X2[i], iy2=Y2[i], ia=AR[i];
            int wend = (nv + 31) >> 5;
            for (int w = (i+1) >> 5; w < wend; ++w) {
                u32 bits = 0u;
                int j0 = max(i+1, w << 5);
                int j1 = min(nv, (w+1) << 5);
                for (int j = j0; j < j1; ++j) {
                    float xx1 = fmaxf(ix1, X1[j]);
                    float yy1 = fmaxf(iy1, Y1[j]);
                    float xx2 = fminf(ix2, X2[j]);
                    float yy2 = fminf(iy2, Y2[j]);
                    float dw = fmaxf(__fsub_rn(xx2, xx1), 0.0f);
                    float dh = fmaxf(__fsub_rn(yy2, yy1), 0.0f);
                    float inter = __fmul_rn(dw, dh);
                    float uni = __fsub_rn(__fadd_rn(ia, AR[j]), inter);
                    bool hit = false;
                    if (uni > 0.0f) hit = (__fdiv_rn(inter, uni) > IOU_T);
                    bits |= ((u32)hit) << (j & 31);
                }
                M[i*16 + w] = bits;
            }
        }
    }
    if (t < 16) {                        // pre-remove invalid tail
        int lo = t*32;
        u32 m;
        if      (nv >= lo + 32) m = 0u;
        else if (nv <= lo)      m = 0xFFFFFFFFu;
        else                    m = ~((1u << (nv - lo)) - 1u);
        rem[t] = m;
    }
    __syncthreads();

    if (t < 32) {                        // serial greedy, warp 0
        int kept = 0;
        for (int i = 0; i < nv; ++i) {
            u32 wv = rem[i >> 5];        // broadcast read
            if (!((wv >> (i & 31)) & 1u)) {
                if (lane == 0) KP[kept] = (short)i;
                kept++;
                if (kept >= NMSMAX) break;
                if (lane < 16) rem[lane] |= M[i*16 + lane];
            }
            __syncwarp();
        }
        if (lane == 0) s_kept = kept;
    }
    __syncthreads();
    int kept = s_kept;
    for (int p = t; p < kept; p += 256) {
        int j = KP[p];
        size_t o = (size_t)b*FLAT + c*NMSMAX + p;
        g_topscore[o] = SC[j];
        float* e = g_flat + o*6;
        e[0] = (float)(c+1);
        e[1] = SC[j];
        e[2] = X1[j]; e[3] = Y1[j]; e[4] = X2[j]; e[5] = Y2[j];
    }
}

// ---------------- kernel 4: per-batch top-200 ----------------
__global__ void k_topk(float* __restrict__ out) {
    __shared__ u64 cur[256];
    __shared__ u64 chk[KC];
    __shared__ int s_cnt;
    int b = blockIdx.x, t = threadIdx.x;
    if (t == 0) s_cnt = 0;
    __syncthreads();

    const float* sc = g_topscore + (size_t)b*FLAT;
    u64* scratch = g_scratch + (size_t)b*FLAT;
    for (int i = t; i < FLAT; i += 256) {
        float s = sc[i];
        if (s > 0.0f) {
            int p = atomicAdd(&s_cnt, 1);
            scratch[p] = ((u64)__float_as_uint(s) << 32) | (u64)(0xFFFFFFFFu - (u32)i);
        }
    }
    __syncthreads();
    int n = s_cnt;              // never mutated after this point
    bool full = (n < TOPK);
    int total = full ? FLAT : n;

    cur[t] = 0ULL;
    __syncthreads();

    int nch = (total + KC - 1)/KC;
    for (int cidx = 0; cidx < nch; ++cidx) {
        int base = cidx*KC;
        #pragma unroll
        for (int r = 0; r < 2; ++r) {
            int i = t + r*256;
            int g = base + i;
            u64 key = 0ULL;
            if (g < total) {
                if (full) {
                    float s = sc[g];
                    key = ((u64)__float_as_uint(s) << 32) | (u64)(0xFFFFFFFFu - (u32)g);
                } else {
                    key = scratch[g];
                }
            }
            chk[i] = key;
        }
        __syncthreads();
        for (int kk = 2; kk <= KC; kk <<= 1) {
            for (int j = kk >> 1; j > 0; j >>= 1) {
                LAYER_BAR(j);
                int i = ((t & ~(j-1)) << 1) | (t & (j-1));
                int p = i | j;
                bool up = ((i & kk) == 0);
                u64 a = chk[i], bb = chk[p];
                if (up ? (a > bb) : (a < bb)) { chk[i] = bb; chk[p] = a; }
            }
        }
        __syncthreads();
        {
            u64 a = cur[t], bb = chk[256 + t];
            cur[t] = (a > bb) ? a : bb;
        }
        for (int j = 128; j > 0; j >>= 1) {
            LAYER_BAR(j);
            if (t < 128) {
                int i = ((t & ~(j-1)) << 1) | (t & (j-1));
                int p = i | j;
                u64 a = cur[i], bb = cur[p];
                if (a < bb) { cur[i] = bb; cur[p] = a; }
            }
        }
        __syncthreads();
    }
    for (int idx = t; idx < TOPK*6; idx += 256) {
        int k = idx / 6, r = idx % 6;
        u64 key = cur[k];
        u32 flat = 0xFFFFFFFFu - (u32)key;
        out[((size_t)b*TOPK + k)*6 + r] = g_flat[((size_t)b*FLAT + flat)*6 + r];
    }
}

// ---------------- launcher ----------------
extern "C" void kernel_launch(void* const* d_in, const int* in_sizes, int n_in,
                              void* d_out, int out_size) {
    const float* y = (const float*)d_in[0];
    float* out = (float*)d_out;

    k_zero<<<7000, 256>>>();
    k_decode<<<dim3((NBOX + TILE_N - 1)/TILE_N, BATCH), 256>>>(y);
    k_select<<<BATCH*NCLS, 256>>>();
    k_nms<<<BATCH*NCLS, 256>>>();
    k_topk<<<BATCH, 256>>>(out);
}

// round 6
// speedup vs baseline: 2.0258x; 1.7220x over previous
#include <cuda_runtime.h>

#define BATCH  32
#define NBOX   8732
#define DDIM   93
#define NCLS   80
#define KC     512
#define PC     1024            // pending buffer capacity
#define NMSMAX 400
#define TOPK   200
#define FLAT   (NCLS*NMSMAX)   // 32000
#define CONF_T 0.01f
#define IOU_T  0.45f
#define NBIN   4096
#define MROW   17               // padded bitmap row (u32 words)

typedef unsigned long long u64;
typedef unsigned int u32;

#define SK(i) ((i) + ((i) >> 5))   // skewed smem index (bank-conflict relief)

// Barrier before a bitonic layer of stride j (prev layer stride 2j).
// Warp w owns elements [64w,64w+64) for strides <=32. Need __syncthreads iff j >= 32.
#define LAYER_BAR(j) do { if ((j) >= 32) __syncthreads(); else __syncwarp(); } while (0)

// ---------------- static scratch (no allocations allowed) ----------------
__device__ float4 g_boxes[BATCH*NBOX];
__device__ float  g_scoresT[(size_t)BATCH*NCLS*NBOX];
__device__ u64    g_cands[(size_t)BATCH*NCLS*KC];
__device__ __align__(16) float g_flat[(size_t)BATCH*FLAT*6];
__device__ __align__(16) float g_topscore[(size_t)BATCH*FLAT];
__device__ u64    g_scratch[(size_t)BATCH*FLAT];

// ---------------- kernel 0: zero the padded flat buffers ----------------
__global__ void k_zero() {
    u32 idx = blockIdx.x*blockDim.x + threadIdx.x;
    const u32 NF = (u32)((size_t)BATCH*FLAT*6/4);
    float4 z = make_float4(0.f,0.f,0.f,0.f);
    if (idx < NF) {
        ((float4*)g_flat)[idx] = z;
    } else {
        u32 j = idx - NF;
        if (j < (u32)((size_t)BATCH*FLAT/4)) ((float4*)g_topscore)[j] = z;
    }
}

// ---------------- kernel 1: decode boxes + transpose scores ----------------
#define TILE_N 64
__global__ void k_decode(const float* __restrict__ y) {
    __shared__ float t[TILE_N*DDIM];
    int b  = blockIdx.y;
    int n0 = blockIdx.x * TILE_N;
    int nn = min(TILE_N, NBOX - n0);
    const float* src = y + ((size_t)b*NBOX + n0)*DDIM;
    for (int i = threadIdx.x; i < nn*DDIM; i += blockDim.x) t[i] = src[i];
    __syncthreads();

    if (threadIdx.x < nn) {
        const float* r = t + threadIdx.x*DDIM;
        float aw = r[87], ah = r[88];
        float cx = __fadd_rn(__fmul_rn(__fmul_rn(r[81], r[89]), aw), r[85]);
        float cy = __fadd_rn(__fmul_rn(__fmul_rn(r[82], r[90]), ah), r[86]);
        float w  = __fmul_rn(expf(__fmul_rn(r[83], r[91])), aw);
        float h  = __fmul_rn(expf(__fmul_rn(r[84], r[92])), ah);
        float xmin = __fmul_rn(__fsub_rn(cx, __fmul_rn(0.5f, w)), 512.0f);
        float ymin = __fmul_rn(__fsub_rn(cy, __fmul_rn(0.5f, h)), 512.0f);
        float xmax = __fmul_rn(__fadd_rn(cx, __fmul_rn(0.5f, w)), 512.0f);
        float ymax = __fmul_rn(__fadd_rn(cy, __fmul_rn(0.5f, h)), 512.0f);
        g_boxes[(size_t)b*NBOX + n0 + threadIdx.x] = make_float4(xmin, ymin, xmax, ymax);
    }
    for (int idx = threadIdx.x; idx < NCLS*TILE_N; idx += blockDim.x) {
        int c = idx / TILE_N, i = idx % TILE_N;
        if (i < nn)
            g_scoresT[((size_t)(b*NCLS + c))*NBOX + n0 + i] = t[i*DDIM + 1 + c];
    }
}

// ---------------- kernel 2: top-512 with histogram-seeded threshold ----------------
// Pass A: 12-bit histogram of score bits [30:19]; pivot bucket B = bucket of the
// 512th-largest. hthr admits exactly buckets >= B (top-512 subset guaranteed).
// Pass B: ballot-compact keys > max(cur[511], hthr) into pending; sort+merge on
// overflow or at the end (typically ONE flush). Exact for any distribution.
__global__ void k_select() {
    __shared__ u64 cur[KC + KC/32];     // 528
    __shared__ u64 pend[PC + PC/32];    // 1056
    __shared__ u32 hist[NBIN];          // 16 KB
    __shared__ int s_pcnt;
    __shared__ u64 s_hthr;
    int task = blockIdx.x;
    int t = threadIdx.x;                // 0..255
    int lane = t & 31;
    const float* sc = g_scoresT + (size_t)task*NBOX;

    cur[SK(t)] = 0ULL; cur[SK(t+256)] = 0ULL;
    #pragma unroll
    for (int r = 0; r < 4; ++r) pend[SK(t + r*256)] = 0ULL;
    #pragma unroll
    for (int r = 0; r < NBIN/256; ++r) hist[t + r*256] = 0u;
    if (t == 0) { s_pcnt = 0; s_hthr = 0ULL; }
    __syncthreads();

    // ---- pass A: histogram ----
    for (int n = t; n < NBOX; n += 256) {
        float s = sc[n];
        if (s > CONF_T) atomicAdd(&hist[__float_as_uint(s) >> 19], 1u);
    }
    __syncthreads();
    if (t < 32) {                       // warp 0: pivot search from the top
        int cum = 0;
        for (int c = NBIN/32 - 1; c >= 0; --c) {
            u32 h = hist[c*32 + lane];
            u32 sfx = h;                // suffix sum over lanes >= lane
            #pragma unroll
            for (int off = 1; off < 32; off <<= 1) {
                u32 v = __shfl_down_sync(0xFFFFFFFFu, sfx, off);
                if (lane + off < 32) sfx += v;
            }
            u32 tot = __shfl_sync(0xFFFFFFFFu, sfx, 0);
            if (cum + (int)tot >= KC) {
                bool cond = (cum + (int)sfx) >= KC;          // monotone in lane
                u32 mask = __ballot_sync(0xFFFFFFFFu, cond); // nonzero (lane 0 true)
                int L = 31 - __clz(mask);
                u32 B = (u32)(c*32 + L);
                if (lane == 0) s_hthr = ((u64)(B << 19)) << 32;
                break;
            }
            cum += (int)tot;
        }
        // if never crossed: fewer than 512 valid -> s_hthr stays 0 (admit all valid)
    }
    __syncthreads();
    u64 hthr = s_hthr;

    // ---- pass B: filtered compaction ----
    const int nch = (NBOX + KC - 1)/KC;     // 18
    for (int cidx = 0; cidx < nch; ++cidx) {
        u64 thr0 = cur[SK(KC-1)];
        u64 thr = (thr0 > hthr) ? thr0 : hthr;
        int base = cidx*KC;
        #pragma unroll
        for (int r = 0; r < 2; ++r) {
            int n = base + t + r*256;
            u64 key = 0ULL;
            if (n < NBOX) {
                float s = sc[n];
                if (s > CONF_T)
                    key = ((u64)__float_as_uint(s) << 32) | (u64)(0xFFFFFFFFu - (u32)n);
            }
            bool pass = key > thr;
            u32 mask = __ballot_sync(0xFFFFFFFFu, pass);
            int rank = __popc(mask & ((1u << lane) - 1u));
            u32 posb = 0;
            if (lane == 0 && mask) posb = atomicAdd(&s_pcnt, __popc(mask));
            posb = __shfl_sync(0xFFFFFFFFu, posb, 0);
            if (pass) {
                u32 pos = posb + rank;
                if (pos < PC) pend[SK(pos)] = key;   // <=1024 by flush invariant
            }
        }
        __syncthreads();
        int p = s_pcnt;
        __syncthreads();   // all threads latch p before next chunk's atomicAdd
        bool last = (cidx == nch - 1);
        if (p > KC || (last && p > 0)) {
            // bitonic sort pend[0..1024) ascending (zeros pad front)
            for (int kk = 2; kk <= PC; kk <<= 1) {
                for (int j = kk >> 1; j > 0; j >>= 1) {
                    LAYER_BAR(j);
                    #pragma unroll
                    for (int r = 0; r < 2; ++r) {
                        int pi = t + r*256;
                        int i = ((pi & ~(j-1)) << 1) | (pi & (j-1));
                        int q = i | j;
                        bool up = ((i & kk) == 0);
                        u64 a = pend[SK(i)], bb = pend[SK(q)];
                        if (up ? (a > bb) : (a < bb)) { pend[SK(i)] = bb; pend[SK(q)] = a; }
                    }
                }
            }
            __syncthreads();
            // cur desc (512) + pending top-512 asc -> elementwise max is bitonic
            {
                u64 a = cur[SK(t)],      bb = pend[SK(KC + t)];
                cur[SK(t)] = (a > bb) ? a : bb;
                u64 a2 = cur[SK(t+256)], b2 = pend[SK(KC + t + 256)];
                cur[SK(t+256)] = (a2 > b2) ? a2 : b2;
            }
            // bitonic merge descending on 512
            for (int j = KC >> 1; j > 0; j >>= 1) {
                LAYER_BAR(j);
                int i = ((t & ~(j-1)) << 1) | (t & (j-1));
                int q = i | j;
                u64 a = cur[SK(i)], bb = cur[SK(q)];
                if (a < bb) { cur[SK(i)] = bb; cur[SK(q)] = a; }
            }
            __syncthreads();
            #pragma unroll
            for (int r = 0; r < 4; ++r) pend[SK(t + r*256)] = 0ULL;
            if (t == 0) s_pcnt = 0;
            __syncthreads();
        }
    }
    g_cands[(size_t)task*KC + t]       = cur[SK(t)];
    g_cands[(size_t)task*KC + t + 256] = cur[SK(t + 256)];
}

// ---------------- kernel 3: bit-matrix greedy NMS ----------------
// Phase 1 (barrier-free, balanced): thread t builds bitmap rows t and 511-t.
// Division-free IOU with exact __fdiv_rn fallback in a ~8e-6 ambiguity band:
// decisions bit-identical to the reference.
// Phase 2: warp-0 serial greedy over MROW-word bitmaps.
__global__ void k_nms() {
    __shared__ float4 B4[KC];            // 8 KB
    __shared__ float AR[KC], SC[KC];     // 4 KB
    __shared__ u32 M[KC*MROW];           // 34816 B
    __shared__ u32 rem[16];
    __shared__ short KP[NMSMAX];
    __shared__ int s_nv, s_kept;
    int task = blockIdx.x;
    int b = task / NCLS, c = task % NCLS;
    int t = threadIdx.x, lane = t & 31;

    if (t == 0) s_nv = KC;
    for (int i = t; i < KC*MROW; i += 256) M[i] = 0u;
    __syncthreads();

    const u64* cand = g_cands + (size_t)task*KC;
    #pragma unroll
    for (int r = 0; r < 2; ++r) {
        int i = t + r*256;
        u64 key = cand[i];
        u32 hi = (u32)(key >> 32);
        float4 bx = make_float4(0.f,0.f,0.f,0.f);
        if (hi != 0u) {
            bx = g_boxes[(size_t)b*NBOX + (0xFFFFFFFFu - (u32)key)];
        } else {
            atomicMin(&s_nv, i);    // keys desc: valid prefix, zero padding after
        }
        B4[i] = bx;
        AR[i] = __fmul_rn(__fsub_rn(bx.z,bx.x), __fsub_rn(bx.w,bx.y));
        SC[i] = __uint_as_float(hi);
    }
    __syncthreads();
    int nv = s_nv;

    #pragma unroll
    for (int rr = 0; rr < 2; ++rr) {
        int i = rr ? (KC-1-t) : t;
        if (i < nv - 1) {
            float4 bi = B4[i];
            float ia = AR[i];
            int wend = (nv + 31) >> 5;
            for (int w = (i+1) >> 5; w < wend; ++w) {
                u32 bits = 0u;
                int j0 = max(i+1, w << 5);
                int j1 = min(nv, (w+1) << 5);
                for (int j = j0; j < j1; ++j) {
                    float4 bj = B4[j];
                    float xx1 = fmaxf(bi.x, bj.x);
                    float yy1 = fmaxf(bi.y, bj.y);
                    float xx2 = fminf(bi.z, bj.z);
                    float yy2 = fminf(bi.w, bj.w);
                    float dw = fmaxf(__fsub_rn(xx2, xx1), 0.0f);
                    float dh = fmaxf(__fsub_rn(yy2, yy1), 0.0f);
                    float inter = __fmul_rn(dw, dh);
                    float uni = __fsub_rn(__fadd_rn(ia, AR[j]), inter);
                    float tq = __fmul_rn(IOU_T, uni);
                    bool hit;
                    if      (inter > __fmul_rn(tq, 1.000004f)) hit = (uni > 0.0f);
                    else if (inter < __fmul_rn(tq, 0.999996f)) hit = false;
                    else hit = (uni > 0.0f) && (__fdiv_rn(inter, uni) > IOU_T);
                    bits |= ((u32)hit) << (j & 31);
                }
                M[i*MROW + w] = bits;
            }
        }
    }
    if (t < 16) {                        // pre-remove invalid tail
        int lo = t*32;
        u32 m;
        if      (nv >= lo + 32) m = 0u;
        else if (nv <= lo)      m = 0xFFFFFFFFu;
        else                    m = ~((1u << (nv - lo)) - 1u);
        rem[t] = m;
    }
    __syncthreads();

    if (t < 32) {                        // serial greedy, warp 0
        int kept = 0;
        for (int i = 0; i < nv; ++i) {
            u32 wv = rem[i >> 5];        // broadcast read
            if (!((wv >> (i & 31)) & 1u)) {
                if (lane == 0) KP[kept] = (short)i;
                kept++;
                if (kept >= NMSMAX) break;
                if (lane < 16) rem[lane] |= M[i*MROW + lane];
            }
            __syncwarp();
        }
        if (lane == 0) s_kept = kept;
    }
    __syncthreads();
    int kept = s_kept;
    for (int p = t; p < kept; p += 256) {
        int j = KP[p];
        float4 bx = B4[j];
        size_t o = (size_t)b*FLAT + c*NMSMAX + p;
        g_topscore[o] = SC[j];
        float* e = g_flat + o*6;
        e[0] = (float)(c+1);
        e[1] = SC[j];
        e[2] = bx.x; e[3] = bx.y; e[4] = bx.z; e[5] = bx.w;
    }
}

// ---------------- kernel 4: per-batch top-200 ----------------
__global__ void k_topk(float* __restrict__ out) {
    __shared__ u64 cur[256];
    __shared__ u64 chk[KC];
    __shared__ int s_cnt;
    int b = blockIdx.x, t = threadIdx.x;
    if (t == 0) s_cnt = 0;
    __syncthreads();

    const float* sc = g_topscore + (size_t)b*FLAT;
    u64* scratch = g_scratch + (size_t)b*FLAT;
    for (int i = t; i < FLAT; i += 256) {
        float s = sc[i];
        if (s > 0.0f) {
            int p = atomicAdd(&s_cnt, 1);
            scratch[p] = ((u64)__float_as_uint(s) << 32) | (u64)(0xFFFFFFFFu - (u32)i);
        }
    }
    __syncthreads();
    int n = s_cnt;              // never mutated after this point
    bool full = (n < TOPK);
    int total = full ? FLAT : n;

    cur[t] = 0ULL;
    __syncthreads();

    int nch = (total + KC - 1)/KC;
    for (int cidx = 0; cidx < nch; ++cidx) {
        int base = cidx*KC;
        #pragma unroll
        for (int r = 0; r < 2; ++r) {
            int i = t + r*256;
            int g = base + i;
            u64 key = 0ULL;
            if (g < total) {
                if (full) {
                    float s = sc[g];
                    key = ((u64)__float_as_uint(s) << 32) | (u64)(0xFFFFFFFFu - (u32)g);
                } else {
                    key = scratch[g];
                }
            }
            chk[i] = key;
        }
        __syncthreads();
        for (int kk = 2; kk <= KC; kk <<= 1) {
            for (int j = kk >> 1; j > 0; j >>= 1) {
                LAYER_BAR(j);
                int i = ((t & ~(j-1)) << 1) | (t & (j-1));
                int p = i | j;
                bool up = ((i & kk) == 0);
                u64 a = chk[i], bb = chk[p];
                if (up ? (a > bb) : (a < bb)) { chk[i] = bb; chk[p] = a; }
            }
        }
        __syncthreads();
        {
            u64 a = cur[t], bb = chk[256 + t];
            cur[t] = (a > bb) ? a : bb;
        }
        for (int j = 128; j > 0; j >>= 1) {
            LAYER_BAR(j);
            if (t < 128) {
                int i = ((t & ~(j-1)) << 1) | (t & (j-1));
                int p = i | j;
                u64 a = cur[i], bb = cur[p];
                if (a < bb) { cur[i] = bb; cur[p] = a; }
            }
        }
        __syncthreads();
    }
    for (int idx = t; idx < TOPK*6; idx += 256) {
        int k = idx / 6, r = idx % 6;
        u64 key = cur[k];
        u32 flat = 0xFFFFFFFFu - (u32)key;
        out[((size_t)b*TOPK + k)*6 + r] = g_flat[((size_t)b*FLAT + flat)*6 + r];
    }
}

// ---------------- launcher ----------------
extern "C" void kernel_launch(void* const* d_in, const int* in_sizes, int n_in,
                              void* d_out, int out_size) {
    const float* y = (const float*)d_in[0];
    float* out = (float*)d_out;

    k_zero<<<7000, 256>>>();
    k_decode<<<dim3((NBOX + TILE_N - 1)/TILE_N, BATCH), 256>>>(y);
    k_select<<<BATCH*NCLS, 256>>>();
    k_nms<<<BATCH*NCLS, 256>>>();
    k_topk<<<BATCH, 256>>>(out);
}